// round 5
// baseline (speedup 1.0000x reference)
#include <cuda_runtime.h>
#include <cfloat>

#define BB 8
#define TT 2048
#define DD 512
#define KQ 32
#define TOPK 4
#define BT (BB*TT)
#define HID 1024
#define NCTA 128

__device__ float g_q[BT*KQ];
__device__ float g_kk[BT*KQ];
__device__ int   g_idx[BT*TOPK];
__device__ float g_gath[BT*DD];
__device__ float g_big[BT*HID];   // GEMM1 hidden, later reused for P
__device__ float g_ffn[BT*DD];
__device__ float g_y[BT*DD];
__device__ float g_hbuf[BB*HID];
__device__ float g_mem[BB*DD];
__device__ unsigned g_arrive[NCTA];
__device__ unsigned g_go;

__device__ __forceinline__ float gelu_exact(float v) {
    return 0.5f * v * (1.0f + erff(v * 0.70710678118654752440f));
}

__device__ __forceinline__ unsigned ld_acq(const unsigned* p) {
    unsigned v; asm volatile("ld.acquire.gpu.u32 %0, [%1];" : "=r"(v) : "l"(p)); return v;
}
__device__ __forceinline__ void st_rel(unsigned* p, unsigned v) {
    asm volatile("st.release.gpu.u32 [%0], %1;" :: "l"(p), "r"(v));
}

__global__ void init_kernel() {
    int t = blockIdx.x * blockDim.x + threadIdx.x;
    if (t < BB*DD) g_mem[t] = 0.0f;
    if (t < NCTA)  g_arrive[t] = 0u;
    if (t == 0)    g_go = 0u;
}

__global__ __launch_bounds__(128) void qk_kernel(
    const float* __restrict__ x, const float* __restrict__ Wq, const float* __restrict__ bq,
    const float* __restrict__ Wk, const float* __restrict__ bk)
{
    __shared__ float xs[4*DD];
    int r0 = blockIdx.x * 4, tid = threadIdx.x;
    for (int i = tid; i < 4*DD; i += 128) xs[i] = x[(size_t)r0*DD + i];
    __syncthreads();
    int r = tid >> 5, j = tid & 31;
    float sq = 0.f, sk = 0.f;
    const float* xr = &xs[r*DD];
    #pragma unroll 8
    for (int d = 0; d < DD; d++) {
        float xv = xr[d];
        sq += xv * Wq[d*KQ + j];
        sk += xv * Wk[d*KQ + j];
    }
    g_q [(size_t)(r0+r)*KQ + j] = sq + bq[j];
    g_kk[(size_t)(r0+r)*KQ + j] = sk + bk[j];
}

__global__ __launch_bounds__(256) void sim_topk_kernel() {
    __shared__ float ks[256*33];
    int b = blockIdx.x >> 8, t0 = (blockIdx.x & 255) * 8;
    int tid = threadIdx.x, warp = tid >> 5, lane = tid & 31;
    int t = t0 + warp;
    float qreg[KQ];
    #pragma unroll
    for (int i = 0; i < KQ; i++) qreg[i] = g_q[((size_t)b*TT + t)*KQ + i];
    float v0=-FLT_MAX,v1=-FLT_MAX,v2=-FLT_MAX,v3=-FLT_MAX;
    int   i0=0x7fffffff,i1=0x7fffffff,i2=0x7fffffff,i3=0x7fffffff;
    for (int c = 0; c < 8; c++) {
        int s0 = c * 256;
        __syncthreads();
        for (int i = tid; i < 256*KQ; i += 256) {
            int sl = i >> 5, kv = i & 31;
            ks[sl*33 + kv] = g_kk[((size_t)b*TT + s0 + sl)*KQ + kv];
        }
        __syncthreads();
        #pragma unroll
        for (int it = 0; it < 8; it++) {
            int sl = (it << 5) + lane;
            const float* kr = &ks[sl*33];
            float sim = 0.f;
            #pragma unroll
            for (int i = 0; i < KQ; i++) sim += qreg[i]*kr[i];
            int s = s0 + sl;
            if (sim > v3) {
                if (sim > v1) {
                    v3=v2;i3=i2; v2=v1;i2=i1;
                    if (sim > v0) { v1=v0;i1=i0; v0=sim;i0=s; }
                    else          { v1=sim;i1=s; }
                } else {
                    if (sim > v2) { v3=v2;i3=i2; v2=sim;i2=s; }
                    else          { v3=sim;i3=s; }
                }
            }
        }
    }
    for (int r = 0; r < 4; r++) {
        float bv = v0; int bi = i0;
        #pragma unroll
        for (int off = 16; off; off >>= 1) {
            float ov = __shfl_xor_sync(0xffffffffu, bv, off);
            int   oi = __shfl_xor_sync(0xffffffffu, bi, off);
            if (ov > bv || (ov == bv && oi < bi)) { bv = ov; bi = oi; }
        }
        if (i0 == bi) { v0=v1;i0=i1; v1=v2;i1=i2; v2=v3;i2=i3; v3=-FLT_MAX;i3=0x7fffffff; }
        if (lane == 0) g_idx[((size_t)b*TT + t)*TOPK + r] = bi;
    }
}

__global__ __launch_bounds__(128) void gather_kernel(const float* __restrict__ x) {
    int bt = blockIdx.x, b = bt >> 11;
    const int4 iv = *(const int4*)&g_idx[(size_t)bt*TOPK];
    const float4* xb = (const float4*)(x + (size_t)b*TT*DD);
    int d = threadIdx.x;
    float4 a = xb[(size_t)iv.x*(DD/4)+d], b4 = xb[(size_t)iv.y*(DD/4)+d];
    float4 c = xb[(size_t)iv.z*(DD/4)+d], e  = xb[(size_t)iv.w*(DD/4)+d];
    float4 m = {0.25f*(a.x+b4.x+c.x+e.x), 0.25f*(a.y+b4.y+c.y+e.y),
                0.25f*(a.z+b4.z+c.z+e.z), 0.25f*(a.w+b4.w+c.w+e.w)};
    ((float4*)(g_gath + (size_t)bt*DD))[d] = m;
}

// C = act(A @ B + bias). MODE 0: g_gath->g_big(gelu); 1: g_big->g_ffn; 2: g_y->g_big
template<int ACT, int MODE>
__global__ __launch_bounds__(256) void sgemm_kernel(
    const float* __restrict__ Bmat, const float* __restrict__ bias, int N, int K)
{
    const float* A = (MODE==0) ? g_gath : (MODE==1) ? g_big : g_y;
    float*       C = (MODE==1) ? g_ffn  : g_big;
    __shared__ float As[16*68];
    __shared__ float Bs[16*68];
    int bm = blockIdx.y * 64, bn = blockIdx.x * 64, tid = threadIdx.x;
    int tx = tid & 15, ty = tid >> 4;
    float acc[4][4] = {};
    int arow = tid >> 2, acol4 = (tid & 3) << 2;
    int brow = tid >> 4, bcol4 = (tid & 15) << 2;
    const float* Aptr = A    + (size_t)(bm + arow) * K + acol4;
    const float* Bptr = Bmat + (size_t)brow * N + bn + bcol4;
    for (int k0 = 0; k0 < K; k0 += 16) {
        float4 av = *(const float4*)Aptr; Aptr += 16;
        float4 bv = *(const float4*)Bptr; Bptr += (size_t)16 * N;
        __syncthreads();
        As[(acol4+0)*68 + arow] = av.x;
        As[(acol4+1)*68 + arow] = av.y;
        As[(acol4+2)*68 + arow] = av.z;
        As[(acol4+3)*68 + arow] = av.w;
        *(float4*)&Bs[brow*68 + bcol4] = bv;
        __syncthreads();
        #pragma unroll
        for (int kk = 0; kk < 16; kk++) {
            float4 a4 = *(const float4*)&As[kk*68 + (ty<<2)];
            float4 b4 = *(const float4*)&Bs[kk*68 + (tx<<2)];
            float ar[4] = {a4.x,a4.y,a4.z,a4.w};
            float br[4] = {b4.x,b4.y,b4.z,b4.w};
            #pragma unroll
            for (int r = 0; r < 4; r++)
                #pragma unroll
                for (int c2 = 0; c2 < 4; c2++) acc[r][c2] += ar[r]*br[c2];
        }
    }
    int row0 = bm + (ty<<2), col0 = bn + (tx<<2);
    float4 bsv = *(const float4*)&bias[col0];
    #pragma unroll
    for (int r = 0; r < 4; r++) {
        float4 v = {acc[r][0]+bsv.x, acc[r][1]+bsv.y, acc[r][2]+bsv.z, acc[r][3]+bsv.w};
        if (ACT) { v.x=gelu_exact(v.x); v.y=gelu_exact(v.y);
                   v.z=gelu_exact(v.z); v.w=gelu_exact(v.w); }
        *(float4*)&C[(size_t)(row0+r)*N + col0] = v;
    }
}

__global__ __launch_bounds__(256) void ln_kernel(
    const float* __restrict__ gamma, const float* __restrict__ beta)
{
    __shared__ float red[8];
    int row = blockIdx.x, tid = threadIdx.x, lane = tid & 31, wid = tid >> 5;
    size_t base = (size_t)row * DD;
    float y0 = g_gath[base+tid]     + g_ffn[base+tid];
    float y1 = g_gath[base+tid+256] + g_ffn[base+tid+256];
    float s = y0 + y1;
    #pragma unroll
    for (int off = 16; off; off >>= 1) s += __shfl_xor_sync(0xffffffffu, s, off);
    if (lane == 0) red[wid] = s;
    __syncthreads();
    float mean = (red[0]+red[1]+red[2]+red[3]+red[4]+red[5]+red[6]+red[7]) * (1.0f/DD);
    __syncthreads();
    float d0 = y0 - mean, d1 = y1 - mean;
    float q = d0*d0 + d1*d1;
    #pragma unroll
    for (int off = 16; off; off >>= 1) q += __shfl_xor_sync(0xffffffffu, q, off);
    if (lane == 0) red[wid] = q;
    __syncthreads();
    float inv = rsqrtf((red[0]+red[1]+red[2]+red[3]+red[4]+red[5]+red[6]+red[7])*(1.0f/DD) + 1e-5f);
    g_y[base+tid]     = d0*inv*gamma[tid]     + beta[tid];
    g_y[base+tid+256] = d1*inv*gamma[tid+256] + beta[tid+256];
}

// Fast grid barrier: acquire/release, no MEMBARs, no contention on arrive slots.
__device__ __forceinline__ void gridbar(unsigned ph) {
    __syncthreads();
    if (blockIdx.x == 0) {
        unsigned t = threadIdx.x;
        if (t >= 1 && t < NCTA) { while (ld_acq(&g_arrive[t]) < ph) {} }
        __syncthreads();
        if (t == 0) st_rel(&g_go, ph);
    } else {
        if (threadIdx.x == 0) {
            st_rel(&g_arrive[blockIdx.x], ph);
            while (ld_acq(&g_go) < ph) {}
        }
        __syncthreads();
    }
}

__global__ __launch_bounds__(256) void scan_kernel(
    const float* __restrict__ Wt1, const float* __restrict__ Wt2,
    const float* __restrict__ bt2)
{
    __shared__ float w1T[8*DD];   // [jj][d] = Wt1[(512+d)*1024 + jc0+jj]
    __shared__ float w2T[4*HID];  // [oo][j] = Wt2[j*512 + oc0+oo]
    int tid = threadIdx.x, lane = tid & 31, b = tid >> 5;
    int jc0 = blockIdx.x * 8, oc0 = blockIdx.x * 4;
    for (int i = tid; i < 8*DD; i += 256) {
        int jj = i >> 9, d = i & (DD-1);
        w1T[i] = Wt1[(size_t)(DD + d)*HID + jc0 + jj];
    }
    for (int i = tid; i < 4*HID; i += 256) {
        int oo = i >> 10, j = i & (HID-1);
        w2T[i] = Wt2[(size_t)j*DD + oc0 + oo];
    }
    __syncthreads();
    float b2r = (lane < 4) ? bt2[oc0 + lane] : 0.f;
    unsigned ph = 1;
    for (int t = 0; t < TT; t++) {
        // prefetch P (independent of mem) to hide its latency behind the barrier
        float pv = (lane < 8) ? __ldg(&g_big[((size_t)b*TT + t)*HID + jc0 + lane]) : 0.f;
        gridbar(ph++);
        {   // hidden slice jc0..jc0+7 for batch b
            float acc[8] = {};
            #pragma unroll
            for (int i = 0; i < 4; i++) {
                int d0 = 128*i + 4*lane;
                float4 m4 = __ldcg((const float4*)&g_mem[b*DD + d0]);
                #pragma unroll
                for (int jj = 0; jj < 8; jj++) {
                    float4 w4 = *(const float4*)&w1T[jj*DD + d0];
                    acc[jj] += m4.x*w4.x + m4.y*w4.y + m4.z*w4.z + m4.w*w4.w;
                }
            }
            #pragma unroll
            for (int off = 16; off; off >>= 1)
                #pragma unroll
                for (int jj = 0; jj < 8; jj++)
                    acc[jj] += __shfl_xor_sync(0xffffffffu, acc[jj], off);
            if (lane < 8) {
                float v = acc[0];
                #pragma unroll
                for (int jj = 1; jj < 8; jj++) if (lane == jj) v = acc[jj];
                v += pv;
                __stcg(&g_hbuf[b*HID + jc0 + lane], gelu_exact(v));
            }
        }
        gridbar(ph++);
        {   // outputs oc0..oc0+3 for batch b
            float acc4[4] = {};
            #pragma unroll
            for (int i = 0; i < 8; i++) {
                int j0 = 128*i + 4*lane;
                float4 h4 = __ldcg((const float4*)&g_hbuf[b*HID + j0]);
                #pragma unroll
                for (int oo = 0; oo < 4; oo++) {
                    float4 w4 = *(const float4*)&w2T[oo*HID + j0];
                    acc4[oo] += h4.x*w4.x + h4.y*w4.y + h4.z*w4.z + h4.w*w4.w;
                }
            }
            #pragma unroll
            for (int off = 16; off; off >>= 1)
                #pragma unroll
                for (int oo = 0; oo < 4; oo++)
                    acc4[oo] += __shfl_xor_sync(0xffffffffu, acc4[oo], off);
            if (lane < 4) {
                float p = acc4[0];
                #pragma unroll
                for (int oo = 1; oo < 4; oo++) if (lane == oo) p = acc4[oo];
                p += b2r;
                int o = oc0 + lane;
                float mo = __ldcg(&g_mem[b*DD + o]);
                float g = 1.0f / (1.0f + expf(-p));
                __stcg(&g_mem[b*DD + o], mo + g*(p - mo));
            }
        }
    }
}

__global__ __launch_bounds__(256) void out_kernel(
    const float* __restrict__ Wo, const float* __restrict__ bo, float* __restrict__ out)
{
    int gid = blockIdx.x*256 + threadIdx.x;
    int b = gid >> 9, o = gid & (DD-1);
    float s = bo[o];
    const float* m = &g_mem[(size_t)b*DD];
    #pragma unroll 8
    for (int d = 0; d < DD; d++) s += m[d] * Wo[(size_t)d*DD + o];
    out[gid] = s;
}

extern "C" void kernel_launch(void* const* d_in, const int* in_sizes, int n_in,
                              void* d_out, int out_size)
{
    const float* x    = (const float*)d_in[0];
    const float* Wq   = (const float*)d_in[1];
    const float* bq   = (const float*)d_in[2];
    const float* Wk   = (const float*)d_in[3];
    const float* bk   = (const float*)d_in[4];
    const float* W1   = (const float*)d_in[5];
    const float* b1   = (const float*)d_in[6];
    const float* W2   = (const float*)d_in[7];
    const float* b2   = (const float*)d_in[8];
    const float* ln_g = (const float*)d_in[9];
    const float* ln_b = (const float*)d_in[10];
    const float* Wt1  = (const float*)d_in[11];
    const float* bt1  = (const float*)d_in[12];
    const float* Wt2  = (const float*)d_in[13];
    const float* bt2  = (const float*)d_in[14];
    const float* Wo   = (const float*)d_in[15];
    const float* bo   = (const float*)d_in[16];
    float* out = (float*)d_out;

    init_kernel<<<16, 256>>>();
    qk_kernel<<<BT/4, 128>>>(x, Wq, bq, Wk, bk);
    sim_topk_kernel<<<BB*(TT/8), 256>>>();
    gather_kernel<<<BT, 128>>>(x);
    {   // GEMM1: [BT,512] @ W1[512,1024] -> gelu -> g_big
        dim3 g(HID/64, BT/64);
        sgemm_kernel<1,0><<<g, 256>>>(W1, b1, HID, DD);
    }
    {   // GEMM2: [BT,1024] @ W2[1024,512] -> g_ffn
        dim3 g(DD/64, BT/64);
        sgemm_kernel<0,1><<<g, 256>>>(W2, b2, DD, HID);
    }
    ln_kernel<<<BT, 256>>>(ln_g, ln_b);
    {   // P-GEMM: g_y[BT,512] @ Wt1[0:512,1024] + bt1 -> g_big
        dim3 g(HID/64, BT/64);
        sgemm_kernel<0,2><<<g, 256>>>(Wt1, bt1, HID, DD);
    }
    scan_kernel<<<NCTA, 256>>>(Wt1, Wt2, bt2);
    out_kernel<<<(BB*DD)/256, 256>>>(Wo, bo, out);
}

// round 6
// speedup vs baseline: 1.1920x; 1.1920x over previous
#include <cuda_runtime.h>
#include <cfloat>

#define BB 8
#define TT 2048
#define DD 512
#define KQ 32
#define TOPK 4
#define BT (BB*TT)
#define HID 1024
#define NCTA 128
#define DP (DD+4)
#define HP (HID+4)

__device__ float g_q[BT*KQ];
__device__ float g_kk[BT*KQ];
__device__ int   g_idx[BT*TOPK];
__device__ float g_gath[BT*DD];
__device__ float g_big[BT*HID];   // GEMM1 hidden, later reused for P
__device__ float g_ffn[BT*DD];
__device__ float g_y[BT*DD];
__device__ float g_hbuf[BB*HID];
__device__ float g_mem[BB*DD];
__device__ unsigned g_arr[NCTA*32];   // padded arrive flags (one 128B line each)

__device__ __forceinline__ float gelu_exact(float v) {
    return 0.5f * v * (1.0f + erff(v * 0.70710678118654752440f));
}
__device__ __forceinline__ unsigned ld_acq(const unsigned* p) {
    unsigned v; asm volatile("ld.acquire.gpu.u32 %0, [%1];" : "=r"(v) : "l"(p)); return v;
}
__device__ __forceinline__ void st_rel(unsigned* p, unsigned v) {
    asm volatile("st.release.gpu.u32 [%0], %1;" :: "l"(p), "r"(v));
}

__global__ void init_kernel() {
    int t = blockIdx.x * blockDim.x + threadIdx.x;
    if (t < BB*DD)   g_mem[t] = 0.0f;
    if (t < NCTA*32) g_arr[t] = 0u;
}

__global__ __launch_bounds__(128) void qk_kernel(
    const float* __restrict__ x, const float* __restrict__ Wq, const float* __restrict__ bq,
    const float* __restrict__ Wk, const float* __restrict__ bk)
{
    __shared__ float xs[4*DD];
    int r0 = blockIdx.x * 4, tid = threadIdx.x;
    for (int i = tid; i < 4*DD; i += 128) xs[i] = x[(size_t)r0*DD + i];
    __syncthreads();
    int r = tid >> 5, j = tid & 31;
    float sq = 0.f, sk = 0.f;
    const float* xr = &xs[r*DD];
    #pragma unroll 8
    for (int d = 0; d < DD; d++) {
        float xv = xr[d];
        sq += xv * Wq[d*KQ + j];
        sk += xv * Wk[d*KQ + j];
    }
    g_q [(size_t)(r0+r)*KQ + j] = sq + bq[j];
    g_kk[(size_t)(r0+r)*KQ + j] = sk + bk[j];
}

__global__ __launch_bounds__(256) void sim_topk_kernel() {
    __shared__ float ks[256*33];
    int b = blockIdx.x >> 8, t0 = (blockIdx.x & 255) * 8;
    int tid = threadIdx.x, warp = tid >> 5, lane = tid & 31;
    int t = t0 + warp;
    float qreg[KQ];
    #pragma unroll
    for (int i = 0; i < KQ; i++) qreg[i] = g_q[((size_t)b*TT + t)*KQ + i];
    float v0=-FLT_MAX,v1=-FLT_MAX,v2=-FLT_MAX,v3=-FLT_MAX;
    int   i0=0x7fffffff,i1=0x7fffffff,i2=0x7fffffff,i3=0x7fffffff;
    for (int c = 0; c < 8; c++) {
        int s0 = c * 256;
        __syncthreads();
        for (int i = tid; i < 256*KQ; i += 256) {
            int sl = i >> 5, kv = i & 31;
            ks[sl*33 + kv] = g_kk[((size_t)b*TT + s0 + sl)*KQ + kv];
        }
        __syncthreads();
        #pragma unroll
        for (int it = 0; it < 8; it++) {
            int sl = (it << 5) + lane;
            const float* kr = &ks[sl*33];
            float sim = 0.f;
            #pragma unroll
            for (int i = 0; i < KQ; i++) sim += qreg[i]*kr[i];
            int s = s0 + sl;
            if (sim > v3) {
                if (sim > v1) {
                    v3=v2;i3=i2; v2=v1;i2=i1;
                    if (sim > v0) { v1=v0;i1=i0; v0=sim;i0=s; }
                    else          { v1=sim;i1=s; }
                } else {
                    if (sim > v2) { v3=v2;i3=i2; v2=sim;i2=s; }
                    else          { v3=sim;i3=s; }
                }
            }
        }
    }
    for (int r = 0; r < 4; r++) {
        float bv = v0; int bi = i0;
        #pragma unroll
        for (int off = 16; off; off >>= 1) {
            float ov = __shfl_xor_sync(0xffffffffu, bv, off);
            int   oi = __shfl_xor_sync(0xffffffffu, bi, off);
            if (ov > bv || (ov == bv && oi < bi)) { bv = ov; bi = oi; }
        }
        if (i0 == bi) { v0=v1;i0=i1; v1=v2;i1=i2; v2=v3;i2=i3; v3=-FLT_MAX;i3=0x7fffffff; }
        if (lane == 0) g_idx[((size_t)b*TT + t)*TOPK + r] = bi;
    }
}

__global__ __launch_bounds__(128) void gather_kernel(const float* __restrict__ x) {
    int bt = blockIdx.x, b = bt >> 11;
    const int4 iv = *(const int4*)&g_idx[(size_t)bt*TOPK];
    const float4* xb = (const float4*)(x + (size_t)b*TT*DD);
    int d = threadIdx.x;
    float4 a = xb[(size_t)iv.x*(DD/4)+d], b4 = xb[(size_t)iv.y*(DD/4)+d];
    float4 c = xb[(size_t)iv.z*(DD/4)+d], e  = xb[(size_t)iv.w*(DD/4)+d];
    float4 m = {0.25f*(a.x+b4.x+c.x+e.x), 0.25f*(a.y+b4.y+c.y+e.y),
                0.25f*(a.z+b4.z+c.z+e.z), 0.25f*(a.w+b4.w+c.w+e.w)};
    ((float4*)(g_gath + (size_t)bt*DD))[d] = m;
}

// C = act(A @ B + bias). MODE 0: g_gath->g_big(gelu); 1: g_big->g_ffn; 2: g_y->g_big
template<int ACT, int MODE>
__global__ __launch_bounds__(256) void sgemm_kernel(
    const float* __restrict__ Bmat, const float* __restrict__ bias, int N, int K)
{
    const float* A = (MODE==0) ? g_gath : (MODE==1) ? g_big : g_y;
    float*       C = (MODE==1) ? g_ffn  : g_big;
    __shared__ float As[16*68];
    __shared__ float Bs[16*68];
    int bm = blockIdx.y * 64, bn = blockIdx.x * 64, tid = threadIdx.x;
    int tx = tid & 15, ty = tid >> 4;
    float acc[4][4] = {};
    int arow = tid >> 2, acol4 = (tid & 3) << 2;
    int brow = tid >> 4, bcol4 = (tid & 15) << 2;
    const float* Aptr = A    + (size_t)(bm + arow) * K + acol4;
    const float* Bptr = Bmat + (size_t)brow * N + bn + bcol4;
    for (int k0 = 0; k0 < K; k0 += 16) {
        float4 av = *(const float4*)Aptr; Aptr += 16;
        float4 bv = *(const float4*)Bptr; Bptr += (size_t)16 * N;
        __syncthreads();
        As[(acol4+0)*68 + arow] = av.x;
        As[(acol4+1)*68 + arow] = av.y;
        As[(acol4+2)*68 + arow] = av.z;
        As[(acol4+3)*68 + arow] = av.w;
        *(float4*)&Bs[brow*68 + bcol4] = bv;
        __syncthreads();
        #pragma unroll
        for (int kk = 0; kk < 16; kk++) {
            float4 a4 = *(const float4*)&As[kk*68 + (ty<<2)];
            float4 b4 = *(const float4*)&Bs[kk*68 + (tx<<2)];
            float ar[4] = {a4.x,a4.y,a4.z,a4.w};
            float br[4] = {b4.x,b4.y,b4.z,b4.w};
            #pragma unroll
            for (int r = 0; r < 4; r++)
                #pragma unroll
                for (int c2 = 0; c2 < 4; c2++) acc[r][c2] += ar[r]*br[c2];
        }
    }
    int row0 = bm + (ty<<2), col0 = bn + (tx<<2);
    float4 bsv = *(const float4*)&bias[col0];
    #pragma unroll
    for (int r = 0; r < 4; r++) {
        float4 v = {acc[r][0]+bsv.x, acc[r][1]+bsv.y, acc[r][2]+bsv.z, acc[r][3]+bsv.w};
        if (ACT) { v.x=gelu_exact(v.x); v.y=gelu_exact(v.y);
                   v.z=gelu_exact(v.z); v.w=gelu_exact(v.w); }
        *(float4*)&C[(size_t)(row0+r)*N + col0] = v;
    }
}

__global__ __launch_bounds__(256) void ln_kernel(
    const float* __restrict__ gamma, const float* __restrict__ beta)
{
    __shared__ float red[8];
    int row = blockIdx.x, tid = threadIdx.x, lane = tid & 31, wid = tid >> 5;
    size_t base = (size_t)row * DD;
    float y0 = g_gath[base+tid]     + g_ffn[base+tid];
    float y1 = g_gath[base+tid+256] + g_ffn[base+tid+256];
    float s = y0 + y1;
    #pragma unroll
    for (int off = 16; off; off >>= 1) s += __shfl_xor_sync(0xffffffffu, s, off);
    if (lane == 0) red[wid] = s;
    __syncthreads();
    float mean = (red[0]+red[1]+red[2]+red[3]+red[4]+red[5]+red[6]+red[7]) * (1.0f/DD);
    __syncthreads();
    float d0 = y0 - mean, d1 = y1 - mean;
    float q = d0*d0 + d1*d1;
    #pragma unroll
    for (int off = 16; off; off >>= 1) q += __shfl_xor_sync(0xffffffffu, q, off);
    if (lane == 0) red[wid] = q;
    __syncthreads();
    float inv = rsqrtf((red[0]+red[1]+red[2]+red[3]+red[4]+red[5]+red[6]+red[7])*(1.0f/DD) + 1e-5f);
    g_y[base+tid]     = d0*inv*gamma[tid]     + beta[tid];
    g_y[base+tid+256] = d1*inv*gamma[tid+256] + beta[tid+256];
}

// One-hop grid barrier: each CTA release-stores its padded flag; every CTA's
// first 128 threads directly acquire-poll all flags. No central aggregator hop.
__device__ __forceinline__ void gridbar(unsigned ph) {
    __syncthreads();
    if (threadIdx.x == 0) st_rel(&g_arr[blockIdx.x*32], ph);
    if (threadIdx.x < NCTA) { while (ld_acq(&g_arr[threadIdx.x*32]) < ph) {} }
    __syncthreads();
}

// dynamic smem layout (floats):
//  w1T : 8*DP      weights Wt1 (mem half), padded rows
//  w2T : 4*HP      weights Wt2, padded rows
//  memS: 8*DP      staged mem_t
//  hS  : 8*HP      staged h_t
//  redA: 8*64      phase-A partials [warp][b*8+j]
//  redB: 8*32      phase-B partials [warp][b*4+o]
#define OFF_W1T  0
#define OFF_W2T  (OFF_W1T + 8*DP)
#define OFF_MEMS (OFF_W2T + 4*HP)
#define OFF_HS   (OFF_MEMS + 8*DP)
#define OFF_REDA (OFF_HS + 8*HP)
#define OFF_REDB (OFF_REDA + 8*64)
#define SCAN_SMEM_FLOATS (OFF_REDB + 8*32)

__global__ __launch_bounds__(256) void scan_kernel(
    const float* __restrict__ Wt1, const float* __restrict__ Wt2,
    const float* __restrict__ bt2)
{
    extern __shared__ float sm[];
    float* w1T  = sm + OFF_W1T;
    float* w2T  = sm + OFF_W2T;
    float* memS = sm + OFF_MEMS;
    float* hS   = sm + OFF_HS;
    float* redA = sm + OFF_REDA;
    float* redB = sm + OFF_REDB;

    int tid = threadIdx.x, lane = tid & 31, w = tid >> 5;
    int jc0 = blockIdx.x * 8, oc0 = blockIdx.x * 4;

    for (int i = tid; i < 8*DD; i += 256) {
        int jj = i >> 9, d = i & (DD-1);
        w1T[jj*DP + d] = Wt1[(size_t)(DD + d)*HID + jc0 + jj];
    }
    for (int i = tid; i < 4*HID; i += 256) {
        int oo = i >> 10, j = i & (HID-1);
        w2T[oo*HP + j] = Wt2[(size_t)j*DD + oc0 + oo];
    }
    __syncthreads();
    float b2r = (tid < 32) ? __ldg(&bt2[oc0 + (tid & 3)]) : 0.f;

    int bA = lane >> 2, j0 = (lane & 3) << 1;       // phase A lane mapping
    int bB = lane >> 2, oB = lane & 3;              // phase B lane mapping

    unsigned ph = 1;
    for (int t = 0; t < TT; t++) {
        // prefetch P for this CTA's 64 (b, j) outputs before the barrier
        float pv = 0.f;
        if (tid < 64) pv = __ldg(&g_big[((size_t)(tid>>3)*TT + t)*HID + jc0 + (tid&7)]);

        gridbar(ph++);                    // mem_t globally visible
        // stage mem [8][512] -> memS (padded rows)
        #pragma unroll
        for (int i = 0; i < 4; i++) {
            int idx = tid + 256*i;        // float4 index, 1024 total
            float4 v = __ldcg((const float4*)g_mem + idx);
            *((float4*)&memS[(idx >> 7) * DP] + (idx & 127)) = v;
        }
        __syncthreads();
        // phase A: warp w covers d in [64w, 64w+64); lane -> (bA, j0/j0+1)
        {
            float a0 = 0.f, a1 = 0.f;
            const float4* mp  = (const float4*)&memS[bA*DP + 64*w];
            const float4* w0p = (const float4*)&w1T[j0*DP + 64*w];
            const float4* w1p = (const float4*)&w1T[(j0+1)*DP + 64*w];
            #pragma unroll
            for (int i = 0; i < 16; i++) {
                float4 m4 = mp[i], u4 = w0p[i], v4 = w1p[i];
                a0 += m4.x*u4.x + m4.y*u4.y + m4.z*u4.z + m4.w*u4.w;
                a1 += m4.x*v4.x + m4.y*v4.y + m4.z*v4.z + m4.w*v4.w;
            }
            *(float2*)&redA[w*64 + bA*8 + j0] = make_float2(a0, a1);
        }
        __syncthreads();
        if (tid < 64) {
            float s = pv;
            #pragma unroll
            for (int k = 0; k < 8; k++) s += redA[k*64 + tid];
            __stcg(&g_hbuf[(tid>>3)*HID + jc0 + (tid&7)], gelu_exact(s));
        }

        gridbar(ph++);                    // h_t globally visible
        // stage h [8][1024] -> hS (padded rows)
        #pragma unroll
        for (int i = 0; i < 8; i++) {
            int idx = tid + 256*i;        // float4 index, 2048 total
            float4 v = __ldcg((const float4*)g_hbuf + idx);
            *((float4*)&hS[(idx >> 8) * HP] + (idx & 255)) = v;
        }
        __syncthreads();
        // phase B: warp w covers j in [128w, 128w+128); lane -> (bB, oB)
        {
            float a0 = 0.f;
            const float4* hp = (const float4*)&hS[bB*HP + 128*w];
            const float4* wp = (const float4*)&w2T[oB*HP + 128*w];
            #pragma unroll
            for (int i = 0; i < 32; i++) {
                float4 h4 = hp[i], w4 = wp[i];
                a0 += h4.x*w4.x + h4.y*w4.y + h4.z*w4.z + h4.w*w4.w;
            }
            redB[w*32 + lane] = a0;
        }
        __syncthreads();
        if (tid < 32) {
            float p = b2r;
            #pragma unroll
            for (int k = 0; k < 8; k++) p += redB[k*32 + tid];
            int b = tid >> 2, o = oc0 + (tid & 3);
            float mo = memS[b*DP + o];
            float g = 1.0f / (1.0f + expf(-p));
            __stcg(&g_mem[b*DD + o], mo + g*(p - mo));
        }
    }
}

__global__ __launch_bounds__(256) void out_kernel(
    const float* __restrict__ Wo, const float* __restrict__ bo, float* __restrict__ out)
{
    int gid = blockIdx.x*256 + threadIdx.x;
    int b = gid >> 9, o = gid & (DD-1);
    float s = bo[o];
    const float* m = &g_mem[(size_t)b*DD];
    #pragma unroll 8
    for (int d = 0; d < DD; d++) s += m[d] * Wo[(size_t)d*DD + o];
    out[gid] = s;
}

extern "C" void kernel_launch(void* const* d_in, const int* in_sizes, int n_in,
                              void* d_out, int out_size)
{
    const float* x    = (const float*)d_in[0];
    const float* Wq   = (const float*)d_in[1];
    const float* bq   = (const float*)d_in[2];
    const float* Wk   = (const float*)d_in[3];
    const float* bk   = (const float*)d_in[4];
    const float* W1   = (const float*)d_in[5];
    const float* b1   = (const float*)d_in[6];
    const float* W2   = (const float*)d_in[7];
    const float* b2   = (const float*)d_in[8];
    const float* ln_g = (const float*)d_in[9];
    const float* ln_b = (const float*)d_in[10];
    const float* Wt1  = (const float*)d_in[11];
    const float* bt1  = (const float*)d_in[12];
    const float* Wt2  = (const float*)d_in[13];
    const float* bt2  = (const float*)d_in[14];
    const float* Wo   = (const float*)d_in[15];
    const float* bo   = (const float*)d_in[16];
    float* out = (float*)d_out;

    static bool attr_done = false;
    if (!attr_done) {
        cudaFuncSetAttribute(scan_kernel, cudaFuncAttributeMaxDynamicSharedMemorySize,
                             SCAN_SMEM_FLOATS * (int)sizeof(float));
        attr_done = true;
    }

    init_kernel<<<16, 256>>>();
    qk_kernel<<<BT/4, 128>>>(x, Wq, bq, Wk, bk);
    sim_topk_kernel<<<BB*(TT/8), 256>>>();
    gather_kernel<<<BT, 128>>>(x);
    {   // GEMM1: [BT,512] @ W1[512,1024] -> gelu -> g_big
        dim3 g(HID/64, BT/64);
        sgemm_kernel<1,0><<<g, 256>>>(W1, b1, HID, DD);
    }
    {   // GEMM2: [BT,1024] @ W2[1024,512] -> g_ffn
        dim3 g(DD/64, BT/64);
        sgemm_kernel<0,1><<<g, 256>>>(W2, b2, DD, HID);
    }
    ln_kernel<<<BT, 256>>>(ln_g, ln_b);
    {   // P-GEMM: g_y[BT,512] @ Wt1[0:512,1024] + bt1 -> g_big
        dim3 g(HID/64, BT/64);
        sgemm_kernel<0,2><<<g, 256>>>(Wt1, bt1, HID, DD);
    }
    scan_kernel<<<NCTA, 256, SCAN_SMEM_FLOATS * (int)sizeof(float)>>>(Wt1, Wt2, bt2);
    out_kernel<<<(BB*DD)/256, 256>>>(Wo, bo, out);
}